// round 7
// baseline (speedup 1.0000x reference)
#include <cuda_runtime.h>
#include <cstdint>
#include <float.h>
#include <math.h>

#define FULLMASK 0xffffffffu
#define EDIM 512
#define MAX_ROWS 4096
#define MAX_V    50432

// ---------- device scratch (static; allocation forbidden) ----------
__device__ float g_projn [(size_t)MAX_ROWS * EDIM];   // normalized projections
__device__ float g_einv  [MAX_V];                     // 1/max(||emb_v||,1e-12)
__device__ float g_pv    [(size_t)MAX_ROWS * 32 * 8]; // per-(row,lane) top-8 vals
__device__ int   g_pi    [(size_t)MAX_ROWS * 32 * 8]; // per-(row,lane) top-8 idx
__device__ float g_tv    [MAX_ROWS * 8];
__device__ int   g_ti    [MAX_ROWS * 8];

// ---------- threefry-2x32, key = jax.random.key(42) -> (0,42) ----------
__device__ __forceinline__ void tf2x32(unsigned c0, unsigned c1,
                                       unsigned& o0, unsigned& o1) {
    unsigned x0 = c0, x1 = c1;
    const unsigned k0 = 0u, k1 = 42u, k2 = 0x1BD11BDAu ^ 0u ^ 42u;
    x0 += k0; x1 += k1;
#define TF_R(r) { x0 += x1; x1 = (x1 << (r)) | (x1 >> (32 - (r))); x1 ^= x0; }
    TF_R(13) TF_R(15) TF_R(26) TF_R(6)   x0 += k1; x1 += k2 + 1u;
    TF_R(17) TF_R(29) TF_R(16) TF_R(24)  x0 += k2; x1 += k0 + 2u;
    TF_R(13) TF_R(15) TF_R(26) TF_R(6)   x0 += k0; x1 += k1 + 3u;
    TF_R(17) TF_R(29) TF_R(16) TF_R(24)  x0 += k1; x1 += k2 + 4u;
    TF_R(13) TF_R(15) TF_R(26) TF_R(6)   x0 += k2; x1 += k0 + 5u;
#undef TF_R
    o0 = x0; o1 = x1;
}

// jax PARTITIONABLE path, bit_width = 32 (jax/_src/prng.py):
//   counts1, counts2 = iota_2x32_shape(shape)   -> (hi, lo) of uint64 flat index
//   bits1, bits2 = threefry2x32(key, (counts1, counts2))
//   return bits1 ^ bits2                        <-- XOR fold, NOT truncation
__device__ __forceinline__ unsigned random_bits_at(unsigned j) {
    unsigned o0, o1;
    tf2x32(0u, j, o0, o1);
    return o0 ^ o1;
}

// gumbel matching jax.random.gumbel float32 (uniform minval=tiny, maxval=1)
__device__ __forceinline__ float gumbel_at(unsigned j) {
    unsigned bits = random_bits_at(j);
    const float TINY = 1.17549435e-38f;
    float f = __uint_as_float((bits >> 9) | 0x3f800000u) - 1.0f;   // [0,1)
    float u = fmaxf(TINY, f * (1.0f - TINY) + TINY);
    return -logf(-logf(u));
}

// ---------- k0: sentinel (float) — diagnostic only ----------
__global__ void sentinel_kernel(float* out, int rows) {
    int r = blockIdx.x * blockDim.x + threadIdx.x;
    if (r < rows) out[r] = 25000.0f;
}

// ---------- k1: embedding inverse norms (one warp / row) ----------
__global__ void einv_kernel(const float* in, int nrows) {
    int w = (blockIdx.x * blockDim.x + threadIdx.x) >> 5;
    int lane = threadIdx.x & 31;
    if (w >= nrows) return;
    const float* x = in + (size_t)w * EDIM;
    float ss = 0.f;
    for (int k = lane; k < EDIM; k += 32) { float v = x[k]; ss += v * v; }
    #pragma unroll
    for (int o = 16; o; o >>= 1) ss += __shfl_xor_sync(FULLMASK, ss, o);
    if (lane == 0) g_einv[w] = 1.0f / fmaxf(sqrtf(ss), 1e-12f);
}

// ---------- k2: projection normalization (exact IEEE div) ----------
__global__ void normp_kernel(const float* in, int nrows) {
    int w = (blockIdx.x * blockDim.x + threadIdx.x) >> 5;
    int lane = threadIdx.x & 31;
    if (w >= nrows) return;
    const float* x = in + (size_t)w * EDIM;
    float ss = 0.f;
    for (int k = lane; k < EDIM; k += 32) { float v = x[k]; ss += v * v; }
    #pragma unroll
    for (int o = 16; o; o >>= 1) ss += __shfl_xor_sync(FULLMASK, ss, o);
    float denom = fmaxf(sqrtf(ss), 1e-12f);
    float* y = g_projn + (size_t)w * EDIM;
    for (int k = lane; k < EDIM; k += 32) y[k] = x[k] / denom;
}

// ---------- top-8 helpers (lax.top_k order: val desc, idx asc) ----------
__device__ __forceinline__ bool better(float v, int i, float v2, int i2) {
    return (v > v2) || (v == v2 && i < i2);
}
__device__ __forceinline__ void ins8(float v, int i, float* tv, int* ti) {
    #pragma unroll
    for (int k = 0; k < 8; k++) {
        bool b = better(v, i, tv[k], ti[k]);
        float nv = b ? v : tv[k];  int ni = b ? i : ti[k];
        float ov = b ? tv[k] : v;  int oi = b ? ti[k] : i;
        tv[k] = nv; ti[k] = ni; v = ov; i = oi;
    }
}

// ---------- k3: fused GEMM + per-thread running top-8 ----------
__global__ void gemm_topk_kernel(const float* emb, int V, int rows) {
    __shared__ float As[32 * 33];
    __shared__ float Bs[32 * 257];
    __shared__ float Si[256];

    const int tid  = threadIdx.x;
    const int lane = tid & 31;
    const int w    = tid >> 5;
    const int rowBase = blockIdx.x * 32;
    const int r0 = w * 4;

    float tv4[4][8]; int ti4[4][8];
    #pragma unroll
    for (int rr = 0; rr < 4; rr++)
        #pragma unroll
        for (int k = 0; k < 8; k++) { tv4[rr][k] = -FLT_MAX; ti4[rr][k] = 0x7FFFFFFF; }

    for (int vbase = 0; vbase < V; vbase += 256) {
        float acc[4][8];
        #pragma unroll
        for (int rr = 0; rr < 4; rr++)
            #pragma unroll
            for (int c = 0; c < 8; c++) acc[rr][c] = 0.f;

        __syncthreads();
        { int vg = vbase + tid; Si[tid] = (vg < V) ? g_einv[vg] : 0.f; }

        for (int k0 = 0; k0 < EDIM; k0 += 32) {
            __syncthreads();
            #pragma unroll
            for (int it = 0; it < 4; it++) {
                int i = tid + it * 256;
                int r = i >> 5, k = i & 31;
                As[r * 33 + k] = g_projn[(size_t)(rowBase + r) * EDIM + k0 + k];
            }
            #pragma unroll
            for (int it = 0; it < 8; it++) {
                int e4 = tid + it * 256;
                int v  = e4 >> 3;
                int k4 = (e4 & 7) * 4;
                int vg = vbase + v;
                float4 val = make_float4(0.f, 0.f, 0.f, 0.f);
                if (vg < V)
                    val = *reinterpret_cast<const float4*>(emb + (size_t)vg * EDIM + k0 + k4);
                float s = Si[v];
                Bs[(k4 + 0) * 257 + v] = val.x * s;
                Bs[(k4 + 1) * 257 + v] = val.y * s;
                Bs[(k4 + 2) * 257 + v] = val.z * s;
                Bs[(k4 + 3) * 257 + v] = val.w * s;
            }
            __syncthreads();

            #pragma unroll 8
            for (int kk = 0; kk < 32; kk++) {
                float a0 = As[(r0 + 0) * 33 + kk];
                float a1 = As[(r0 + 1) * 33 + kk];
                float a2 = As[(r0 + 2) * 33 + kk];
                float a3 = As[(r0 + 3) * 33 + kk];
                const float* brow = Bs + kk * 257 + lane;
                #pragma unroll
                for (int c = 0; c < 8; c++) {
                    float b = brow[c * 32];
                    acc[0][c] = fmaf(a0, b, acc[0][c]);
                    acc[1][c] = fmaf(a1, b, acc[1][c]);
                    acc[2][c] = fmaf(a2, b, acc[2][c]);
                    acc[3][c] = fmaf(a3, b, acc[3][c]);
                }
            }
        }

        #pragma unroll
        for (int rr = 0; rr < 4; rr++)
            #pragma unroll
            for (int c = 0; c < 8; c++) {
                int vg = vbase + c * 32 + lane;
                float v = acc[rr][c];
                if (vg < V && better(v, vg, tv4[rr][7], ti4[rr][7]))
                    ins8(v, vg, tv4[rr], ti4[rr]);
            }
    }

    #pragma unroll
    for (int rr = 0; rr < 4; rr++) {
        size_t base = ((size_t)(rowBase + r0 + rr) * 32 + lane) * 8;
        #pragma unroll
        for (int k = 0; k < 8; k++) { g_pv[base + k] = tv4[rr][k]; g_pi[base + k] = ti4[rr][k]; }
    }
}

// ---------- k4: merge 32 lane-lists per row ----------
__global__ void merge_kernel(int rows) {
    int r = blockIdx.x * blockDim.x + threadIdx.x;
    if (r >= rows) return;
    float mv[8]; int mi[8];
    #pragma unroll
    for (int k = 0; k < 8; k++) { mv[k] = -FLT_MAX; mi[k] = 0x7FFFFFFF; }
    size_t base = (size_t)r * 32 * 8;
    for (int t = 0; t < 32 * 8; t++) {
        float f = g_pv[base + t]; int i = g_pi[base + t];
        if (better(f, i, mv[7], mi[7])) ins8(f, i, mv, mi);
    }
    #pragma unroll
    for (int k = 0; k < 8; k++) { g_tv[r * 8 + k] = mv[k]; g_ti[r * 8 + k] = mi[k]; }
}

// ---------- k5: gumbel-argmax sampling (partitionable xor-fold stream) ----------
__global__ void sample_kernel(int rows, float* out) {
    int r = blockIdx.x * blockDim.x + threadIdx.x;
    if (r >= rows) return;
    float best = -FLT_MAX; int bi = 0;
    #pragma unroll
    for (int k = 0; k < 8; k++) {
        float s = g_tv[r * 8 + k] + gumbel_at((unsigned)(r * 8 + k));
        if (s > best) { best = s; bi = k; }   // first max wins == jnp.argmax
    }
    out[r] = (float)g_ti[r * 8 + bi];         // tokens stored as float32
}

// ---------- launch ----------
extern "C" void kernel_launch(void* const* d_in, const int* in_sizes, int n_in,
                              void* d_out, int out_size)
{
    int pidx = 0, eidx = 1;
    if (n_in >= 2 && in_sizes[0] > in_sizes[1]) { pidx = 1; eidx = 0; }
    const float* proj = (const float*)d_in[pidx];
    const float* emb  = (const float*)d_in[eidx];

    int rows = out_size;                       // B*S = 4096
    if (rows <= 0 || rows > MAX_ROWS) rows = in_sizes[pidx] / EDIM;
    int V = in_sizes[eidx] / EDIM;             // 50257
    if (V > MAX_V) V = MAX_V;
    float* out = (float*)d_out;

    sentinel_kernel<<<(rows + 255) / 256, 256>>>(out, rows);
    einv_kernel<<<(V * 32 + 255) / 256, 256>>>(emb, V);
    normp_kernel<<<(rows * 32 + 255) / 256, 256>>>(proj, rows);
    gemm_topk_kernel<<<rows / 32, 256>>>(emb, V, rows);
    merge_kernel<<<(rows + 255) / 256, 256>>>(rows);
    sample_kernel<<<(rows + 255) / 256, 256>>>(rows, out);
}

// round 8
// speedup vs baseline: 1.0694x; 1.0694x over previous
#include <cuda_runtime.h>
#include <cstdint>
#include <float.h>
#include <math.h>

#define FULLMASK 0xffffffffu
#define EDIM 512
#define MAX_ROWS 4096
#define MAX_V    50432
#define VSPLIT   4

// ---------- device scratch (static; allocation forbidden) ----------
__device__ float g_projn [(size_t)MAX_ROWS * EDIM];
__device__ float g_einv  [MAX_V];
__device__ float g_pv    [(size_t)MAX_ROWS * VSPLIT * 32 * 8];   // 16 MB
__device__ int   g_pi    [(size_t)MAX_ROWS * VSPLIT * 32 * 8];   // 16 MB
__device__ float g_tv    [MAX_ROWS * 8];
__device__ int   g_ti    [MAX_ROWS * 8];

// ---------- threefry-2x32, key = jax.random.key(42) -> (0,42) ----------
__device__ __forceinline__ void tf2x32(unsigned c0, unsigned c1,
                                       unsigned& o0, unsigned& o1) {
    unsigned x0 = c0, x1 = c1;
    const unsigned k0 = 0u, k1 = 42u, k2 = 0x1BD11BDAu ^ 0u ^ 42u;
    x0 += k0; x1 += k1;
#define TF_R(r) { x0 += x1; x1 = (x1 << (r)) | (x1 >> (32 - (r))); x1 ^= x0; }
    TF_R(13) TF_R(15) TF_R(26) TF_R(6)   x0 += k1; x1 += k2 + 1u;
    TF_R(17) TF_R(29) TF_R(16) TF_R(24)  x0 += k2; x1 += k0 + 2u;
    TF_R(13) TF_R(15) TF_R(26) TF_R(6)   x0 += k0; x1 += k1 + 3u;
    TF_R(17) TF_R(29) TF_R(16) TF_R(24)  x0 += k1; x1 += k2 + 4u;
    TF_R(13) TF_R(15) TF_R(26) TF_R(6)   x0 += k2; x1 += k0 + 5u;
#undef TF_R
    o0 = x0; o1 = x1;
}
// jax partitionable path, 32-bit: counter=(0,j), bits = o0 ^ o1  (VERIFIED rel_err=0)
__device__ __forceinline__ float gumbel_at(unsigned j) {
    unsigned o0, o1; tf2x32(0u, j, o0, o1);
    unsigned bits = o0 ^ o1;
    const float TINY = 1.17549435e-38f;
    float f = __uint_as_float((bits >> 9) | 0x3f800000u) - 1.0f;
    float u = fmaxf(TINY, f * (1.0f - TINY) + TINY);
    return -logf(-logf(u));
}

// ---------- embedding inverse norms ----------
__global__ void einv_kernel(const float* in, int nrows) {
    int w = (blockIdx.x * blockDim.x + threadIdx.x) >> 5;
    int lane = threadIdx.x & 31;
    if (w >= nrows) return;
    const float* x = in + (size_t)w * EDIM;
    float ss = 0.f;
    for (int k = lane; k < EDIM; k += 32) { float v = x[k]; ss += v * v; }
    #pragma unroll
    for (int o = 16; o; o >>= 1) ss += __shfl_xor_sync(FULLMASK, ss, o);
    if (lane == 0) g_einv[w] = 1.0f / fmaxf(sqrtf(ss), 1e-12f);
}

// ---------- projection normalization (IEEE div) ----------
__global__ void normp_kernel(const float* in, int nrows) {
    int w = (blockIdx.x * blockDim.x + threadIdx.x) >> 5;
    int lane = threadIdx.x & 31;
    if (w >= nrows) return;
    const float* x = in + (size_t)w * EDIM;
    float ss = 0.f;
    for (int k = lane; k < EDIM; k += 32) { float v = x[k]; ss += v * v; }
    #pragma unroll
    for (int o = 16; o; o >>= 1) ss += __shfl_xor_sync(FULLMASK, ss, o);
    float denom = fmaxf(sqrtf(ss), 1e-12f);
    float* y = g_projn + (size_t)w * EDIM;
    for (int k = lane; k < EDIM; k += 32) y[k] = x[k] / denom;
}

// ---------- top-8 helpers (lax.top_k order: val desc, idx asc) ----------
__device__ __forceinline__ bool better(float v, int i, float v2, int i2) {
    return (v > v2) || (v == v2 && i < i2);
}
__device__ __forceinline__ void ins8(float v, int i, float* tv, int* ti) {
    #pragma unroll
    for (int k = 0; k < 8; k++) {
        bool b = better(v, i, tv[k], ti[k]);
        float nv = b ? v : tv[k];  int ni = b ? i : ti[k];
        float ov = b ? tv[k] : v;  int oi = b ? ti[k] : i;
        tv[k] = nv; ti[k] = ni; v = ov; i = oi;
    }
}

// ---------- fused GEMM + per-thread running top-8, vectorized ----------
// grid = (rows/32, VSPLIT), 256 threads. Warp w owns rows r0..r0+3 and all
// 256 cols of each V-tile (lane -> cols lane*8..lane*8+7). Inner loop:
// 1 LDS.128 (A bcast) + 2 LDS.128 (B) + 32 FFMA per k.
__global__ __launch_bounds__(256, 2) void gemm_topk_kernel(
    const float* __restrict__ emb, int V, int rows)
{
    __shared__ float As[16][32];      // [kk][row]   2 KB
    __shared__ float Bs[16][256];     // [kk][col]  16 KB

    const int tid  = threadIdx.x;
    const int lane = tid & 31;
    const int w    = tid >> 5;
    const int rowBase = blockIdx.x * 32;
    const int split   = blockIdx.y;
    const int r0 = w * 4;

    const int vtilesTotal = (V + 255) / 256;                 // 197
    const int per = (vtilesTotal + VSPLIT - 1) / VSPLIT;     // 50
    const int t0 = split * per;
    const int t1 = min(vtilesTotal, t0 + per);

    float tv4[4][8]; int ti4[4][8];
    #pragma unroll
    for (int rr = 0; rr < 4; rr++)
        #pragma unroll
        for (int k = 0; k < 8; k++) { tv4[rr][k] = -FLT_MAX; ti4[rr][k] = 0x7FFFFFFF; }

    for (int vt = t0; vt < t1; vt++) {
        const int vbase = vt * 256;
        const int vg_me = vbase + tid;                       // this thread's B row
        const float sc  = (vg_me < V) ? g_einv[vg_me] : 0.f;
        const float* brow_g = emb + (size_t)(vg_me < V ? vg_me : 0) * EDIM;

        float acc[4][8];
        #pragma unroll
        for (int rr = 0; rr < 4; rr++)
            #pragma unroll
            for (int c = 0; c < 8; c++) acc[rr][c] = 0.f;

        for (int k0 = 0; k0 < EDIM; k0 += 16) {
            __syncthreads();
            // A: 32 rows x 16 k, transposed to [kk][row]
            if (tid < 128) {
                int r = tid >> 2, k4 = (tid & 3) * 4;
                float4 av = *reinterpret_cast<const float4*>(
                    g_projn + (size_t)(rowBase + r) * EDIM + k0 + k4);
                As[k4 + 0][r] = av.x; As[k4 + 1][r] = av.y;
                As[k4 + 2][r] = av.z; As[k4 + 3][r] = av.w;
            }
            // B: 256 vocab rows x 16 k, transposed to [kk][col], pre-scaled
            #pragma unroll
            for (int c4 = 0; c4 < 4; c4++) {
                float4 bv = (vg_me < V)
                    ? *reinterpret_cast<const float4*>(brow_g + k0 + c4 * 4)
                    : make_float4(0.f, 0.f, 0.f, 0.f);
                Bs[c4 * 4 + 0][tid] = bv.x * sc;
                Bs[c4 * 4 + 1][tid] = bv.y * sc;
                Bs[c4 * 4 + 2][tid] = bv.z * sc;
                Bs[c4 * 4 + 3][tid] = bv.w * sc;
            }
            __syncthreads();

            #pragma unroll
            for (int kk = 0; kk < 16; kk++) {
                float4 a4 = *reinterpret_cast<const float4*>(&As[kk][r0]);   // bcast
                const float* bp = &Bs[kk][lane * 8];
                float4 b0 = *reinterpret_cast<const float4*>(bp);
                float4 b1 = *reinterpret_cast<const float4*>(bp + 4);
                float bb[8] = {b0.x, b0.y, b0.z, b0.w, b1.x, b1.y, b1.z, b1.w};
                #pragma unroll
                for (int c = 0; c < 8; c++) {
                    acc[0][c] = fmaf(a4.x, bb[c], acc[0][c]);
                    acc[1][c] = fmaf(a4.y, bb[c], acc[1][c]);
                    acc[2][c] = fmaf(a4.z, bb[c], acc[2][c]);
                    acc[3][c] = fmaf(a4.w, bb[c], acc[3][c]);
                }
            }
        }

        // merge this tile's candidates (cols lane*8..lane*8+7)
        #pragma unroll
        for (int rr = 0; rr < 4; rr++)
            #pragma unroll
            for (int c = 0; c < 8; c++) {
                int vg = vbase + lane * 8 + c;
                float v = acc[rr][c];
                if (vg < V && better(v, vg, tv4[rr][7], ti4[rr][7]))
                    ins8(v, vg, tv4[rr], ti4[rr]);
            }
    }

    // dump: g_pv[((row*VSPLIT + split)*32 + lane)*8 + k]
    #pragma unroll
    for (int rr = 0; rr < 4; rr++) {
        int row = rowBase + r0 + rr;
        size_t base = (((size_t)row * VSPLIT + split) * 32 + lane) * 8;
        #pragma unroll
        for (int k = 0; k < 8; k++) { g_pv[base + k] = tv4[rr][k]; g_pi[base + k] = ti4[rr][k]; }
    }
}

// ---------- merge VSPLIT*32 lane-lists per row ----------
__global__ void merge_kernel(int rows) {
    int r = blockIdx.x * blockDim.x + threadIdx.x;
    if (r >= rows) return;
    float mv[8]; int mi[8];
    #pragma unroll
    for (int k = 0; k < 8; k++) { mv[k] = -FLT_MAX; mi[k] = 0x7FFFFFFF; }
    size_t base = (size_t)r * VSPLIT * 32 * 8;
    for (int t = 0; t < VSPLIT * 32 * 8; t++) {
        float f = g_pv[base + t]; int i = g_pi[base + t];
        if (better(f, i, mv[7], mi[7])) ins8(f, i, mv, mi);
    }
    #pragma unroll
    for (int k = 0; k < 8; k++) { g_tv[r * 8 + k] = mv[k]; g_ti[r * 8 + k] = mi[k]; }
}

// ---------- gumbel-argmax sampling; float32 output ----------
__global__ void sample_kernel(int rows, float* out) {
    int r = blockIdx.x * blockDim.x + threadIdx.x;
    if (r >= rows) return;
    float best = -FLT_MAX; int bi = 0;
    #pragma unroll
    for (int k = 0; k < 8; k++) {
        float s = g_tv[r * 8 + k] + gumbel_at((unsigned)(r * 8 + k));
        if (s > best) { best = s; bi = k; }
    }
    out[r] = (float)g_ti[r * 8 + bi];
}

// ---------- launch ----------
extern "C" void kernel_launch(void* const* d_in, const int* in_sizes, int n_in,
                              void* d_out, int out_size)
{
    int pidx = 0, eidx = 1;
    if (n_in >= 2 && in_sizes[0] > in_sizes[1]) { pidx = 1; eidx = 0; }
    const float* proj = (const float*)d_in[pidx];
    const float* emb  = (const float*)d_in[eidx];

    int rows = out_size;
    if (rows <= 0 || rows > MAX_ROWS) rows = in_sizes[pidx] / EDIM;
    int V = in_sizes[eidx] / EDIM;
    if (V > MAX_V) V = MAX_V;
    float* out = (float*)d_out;

    einv_kernel<<<(V * 32 + 255) / 256, 256>>>(emb, V);
    normp_kernel<<<(rows * 32 + 255) / 256, 256>>>(proj, rows);

    dim3 grid(rows / 32, VSPLIT);
    gemm_topk_kernel<<<grid, 256>>>(emb, V, rows);

    merge_kernel<<<(rows + 255) / 256, 256>>>(rows);
    sample_kernel<<<(rows + 255) / 256, 256>>>(rows, out);
}

// round 11
// speedup vs baseline: 4.6516x; 4.3497x over previous
#include <cuda_runtime.h>
#include <mma.h>
#include <cstdint>
#include <float.h>
#include <math.h>

using namespace nvcuda;

#define FULLMASK 0xffffffffu
#define EDIM 512
#define MAX_ROWS 4096
#define MAX_V    50432
#define VSPLIT   9
#define NLISTS   (VSPLIT * 4)        // lists per row
#define KC       16                  // k-chunk
#define AST      20                  // As stride (floats)
#define BST      20                  // Bs stride (floats)
#define WBST     20                  // extraction buffer stride

// ---------- device scratch ----------
__device__ float g_projn [(size_t)MAX_ROWS * EDIM];
__device__ float g_einv  [MAX_V];
__device__ float g_pv    [(size_t)MAX_ROWS * NLISTS * 8];
__device__ int   g_pi    [(size_t)MAX_ROWS * NLISTS * 8];
__device__ int   g_ci    [MAX_ROWS * 16];                 // top-16 candidate indices
__device__ float g_tv    [MAX_ROWS * 8];
__device__ int   g_ti    [MAX_ROWS * 8];

// ---------- threefry-2x32, key=(0,42); partitionable xor-fold (VERIFIED) ----------
__device__ __forceinline__ void tf2x32(unsigned c0, unsigned c1,
                                       unsigned& o0, unsigned& o1) {
    unsigned x0 = c0, x1 = c1;
    const unsigned k0 = 0u, k1 = 42u, k2 = 0x1BD11BDAu ^ 0u ^ 42u;
    x0 += k0; x1 += k1;
#define TF_R(r) { x0 += x1; x1 = (x1 << (r)) | (x1 >> (32 - (r))); x1 ^= x0; }
    TF_R(13) TF_R(15) TF_R(26) TF_R(6)   x0 += k1; x1 += k2 + 1u;
    TF_R(17) TF_R(29) TF_R(16) TF_R(24)  x0 += k2; x1 += k0 + 2u;
    TF_R(13) TF_R(15) TF_R(26) TF_R(6)   x0 += k0; x1 += k1 + 3u;
    TF_R(17) TF_R(29) TF_R(16) TF_R(24)  x0 += k1; x1 += k2 + 4u;
    TF_R(13) TF_R(15) TF_R(26) TF_R(6)   x0 += k2; x1 += k0 + 5u;
#undef TF_R
    o0 = x0; o1 = x1;
}
__device__ __forceinline__ float gumbel_at(unsigned j) {
    unsigned o0, o1; tf2x32(0u, j, o0, o1);
    unsigned bits = o0 ^ o1;
    const float TINY = 1.17549435e-38f;
    float f = __uint_as_float((bits >> 9) | 0x3f800000u) - 1.0f;
    float u = fmaxf(TINY, f * (1.0f - TINY) + TINY);
    return -logf(-logf(u));
}

__device__ __forceinline__ float to_tf32(float x) {
    float r; asm("cvt.rna.tf32.f32 %0, %1;" : "=f"(r) : "f"(x)); return r;
}

// ---------- norms ----------
__global__ void einv_kernel(const float* in, int nrows) {
    int w = (blockIdx.x * blockDim.x + threadIdx.x) >> 5;
    int lane = threadIdx.x & 31;
    if (w >= nrows) return;
    const float* x = in + (size_t)w * EDIM;
    float ss = 0.f;
    for (int k = lane; k < EDIM; k += 32) { float v = x[k]; ss += v * v; }
    #pragma unroll
    for (int o = 16; o; o >>= 1) ss += __shfl_xor_sync(FULLMASK, ss, o);
    if (lane == 0) g_einv[w] = 1.0f / fmaxf(sqrtf(ss), 1e-12f);
}
__global__ void normp_kernel(const float* in, int nrows) {
    int w = (blockIdx.x * blockDim.x + threadIdx.x) >> 5;
    int lane = threadIdx.x & 31;
    if (w >= nrows) return;
    const float* x = in + (size_t)w * EDIM;
    float ss = 0.f;
    for (int k = lane; k < EDIM; k += 32) { float v = x[k]; ss += v * v; }
    #pragma unroll
    for (int o = 16; o; o >>= 1) ss += __shfl_xor_sync(FULLMASK, ss, o);
    float denom = fmaxf(sqrtf(ss), 1e-12f);
    float* y = g_projn + (size_t)w * EDIM;
    for (int k = lane; k < EDIM; k += 32) y[k] = x[k] / denom;
}

// ---------- top-k helpers (lax.top_k order) ----------
__device__ __forceinline__ bool better(float v, int i, float v2, int i2) {
    return (v > v2) || (v == v2 && i < i2);
}
__device__ __forceinline__ void ins8(float v, int i, float* tv, int* ti) {
    #pragma unroll
    for (int k = 0; k < 8; k++) {
        bool b = better(v, i, tv[k], ti[k]);
        float nv = b ? v : tv[k];  int ni = b ? i : ti[k];
        float ov = b ? tv[k] : v;  int oi = b ? ti[k] : i;
        tv[k] = nv; ti[k] = ni; v = ov; i = oi;
    }
}
__device__ __forceinline__ void ins16(float v, int i, float* tv, int* ti) {
    #pragma unroll
    for (int k = 0; k < 16; k++) {
        bool b = better(v, i, tv[k], ti[k]);
        float nv = b ? v : tv[k];  int ni = b ? i : ti[k];
        float ov = b ? tv[k] : v;  int oi = b ? ti[k] : i;
        tv[k] = nv; ti[k] = ni; v = ov; i = oi;
    }
}

// ---------- coarse tf32 WMMA GEMM + per-warp-range top-8 candidates ----------
// grid (rows/128, VSPLIT), 512 threads (16 warps: rw = w/4 rows, cw = w%4 cols).
// Block tile 128x256, warp tile 32x64 (2x4 m16n16k8 frags), KC=16.
__global__ __launch_bounds__(512, 1) void coarse_kernel(
    const float* __restrict__ emb, int V, int rows)
{
    __shared__ float pool[16 * 32 * WBST];   // 40 KB; also holds As/Bs
    float* As = pool;                        // [128][AST]  2560 floats
    float* Bs = pool + 128 * AST;            // [256][BST]  5120 floats

    const int tid  = threadIdx.x;
    const int lane = tid & 31;
    const int w    = tid >> 5;
    const int rw   = w >> 2;                 // 0..3
    const int cw   = w & 3;                  // 0..3
    const int rowBase = blockIdx.x * 128;
    const int split   = blockIdx.y;

    const int vtilesTotal = (V + 255) / 256;
    const int per = (vtilesTotal + VSPLIT - 1) / VSPLIT;
    const int t0 = split * per;
    const int t1 = min(vtilesTotal, t0 + per);

    float tv[8]; int ti[8];
    #pragma unroll
    for (int k = 0; k < 8; k++) { tv[k] = -FLT_MAX; ti[k] = 0x7FFFFFFF; }

    wmma::fragment<wmma::accumulator, 16, 16, 8, float> acc[2][4];

    for (int vt = t0; vt < t1; vt++) {
        const int vbase = vt * 256;
        #pragma unroll
        for (int f = 0; f < 2; f++)
            #pragma unroll
            for (int c = 0; c < 4; c++) wmma::fill_fragment(acc[f][c], 0.0f);

        for (int k0 = 0; k0 < EDIM; k0 += KC) {
            __syncthreads();
            // A fill: 128 rows x 16 k, 1 float4/thread
            {
                int r = tid >> 2, kq = (tid & 3) * 4;
                float4 av = *reinterpret_cast<const float4*>(
                    g_projn + (size_t)(rowBase + r) * EDIM + k0 + kq);
                float* d = As + r * AST + kq;
                d[0] = to_tf32(av.x); d[1] = to_tf32(av.y);
                d[2] = to_tf32(av.z); d[3] = to_tf32(av.w);
            }
            // B fill: 256 vocab rows x 16 k, 2 float4/thread, pre-scaled
            {
                int vr = tid >> 1, kq = (tid & 1) * 8;
                int vg = vbase + vr;
                float sc = (vg < V) ? g_einv[vg] : 0.f;
                const float* src = emb + (size_t)(vg < V ? vg : 0) * EDIM + k0 + kq;
                float4 b0 = (vg < V) ? *reinterpret_cast<const float4*>(src)
                                     : make_float4(0.f, 0.f, 0.f, 0.f);
                float4 b1 = (vg < V) ? *reinterpret_cast<const float4*>(src + 4)
                                     : make_float4(0.f, 0.f, 0.f, 0.f);
                float* d = Bs + vr * BST + kq;
                d[0] = to_tf32(b0.x * sc); d[1] = to_tf32(b0.y * sc);
                d[2] = to_tf32(b0.z * sc); d[3] = to_tf32(b0.w * sc);
                d[4] = to_tf32(b1.x * sc); d[5] = to_tf32(b1.y * sc);
                d[6] = to_tf32(b1.z * sc); d[7] = to_tf32(b1.w * sc);
            }
            __syncthreads();

            #pragma unroll
            for (int ks = 0; ks < KC / 8; ks++) {
                wmma::fragment<wmma::matrix_a, 16, 16, 8, wmma::precision::tf32,
                               wmma::row_major> fa[2];
                wmma::fragment<wmma::matrix_b, 16, 16, 8, wmma::precision::tf32,
                               wmma::col_major> fb[4];
                #pragma unroll
                for (int f = 0; f < 2; f++)
                    wmma::load_matrix_sync(fa[f], As + (rw * 32 + f * 16) * AST + ks * 8, AST);
                #pragma unroll
                for (int c = 0; c < 4; c++)
                    wmma::load_matrix_sync(fb[c], Bs + (cw * 64 + c * 16) * BST + ks * 8, BST);
                #pragma unroll
                for (int f = 0; f < 2; f++)
                    #pragma unroll
                    for (int c = 0; c < 4; c++)
                        wmma::mma_sync(acc[f][c], fa[f], fb[c], acc[f][c]);
            }
        }

        __syncthreads();   // all warps done reading Bs before pool reuse
        // extraction: per warp buffer 32x20, one fcol (16 cols) at a time
        float* wbuf = pool + w * 32 * WBST;
        #pragma unroll
        for (int c = 0; c < 4; c++) {
            wmma::store_matrix_sync(wbuf,             acc[0][c], WBST, wmma::mem_row_major);
            wmma::store_matrix_sync(wbuf + 16 * WBST, acc[1][c], WBST, wmma::mem_row_major);
            __syncwarp();
            const float* myrow = wbuf + lane * WBST;
            #pragma unroll
            for (int j = 0; j < 16; j++) {
                int idx = vbase + cw * 64 + c * 16 + j;
                float v = myrow[j];
                if (idx < V && better(v, idx, tv[7], ti[7])) ins8(v, idx, tv, ti);
            }
            __syncwarp();
        }
    }

    // dump list: row = rowBase + rw*32 + lane, list = split*4 + cw
    {
        int row = rowBase + rw * 32 + lane;
        size_t base = ((size_t)row * NLISTS + split * 4 + cw) * 8;
        #pragma unroll
        for (int k = 0; k < 8; k++) { g_pv[base + k] = tv[k]; g_pi[base + k] = ti[k]; }
    }
}

// ---------- merge NLISTS*8 coarse entries per row -> top-16 candidate indices ----
__global__ void merge_kernel(int rows) {
    int r = blockIdx.x * blockDim.x + threadIdx.x;
    if (r >= rows) return;
    float mv[16]; int mi[16];
    #pragma unroll
    for (int k = 0; k < 16; k++) { mv[k] = -FLT_MAX; mi[k] = 0x7FFFFFFF; }
    size_t base = (size_t)r * NLISTS * 8;
    for (int t = 0; t < NLISTS * 8; t++) {
        float f = g_pv[base + t]; int i = g_pi[base + t];
        if (better(f, i, mv[15], mi[15])) ins16(f, i, mv, mi);
    }
    #pragma unroll
    for (int k = 0; k < 16; k++) g_ci[r * 16 + k] = mi[k];
}

// ---------- fp32 exact rescore of 16 candidates -> top-8 ----------
__global__ void rescore_kernel(const float* __restrict__ emb, int rows) {
    __shared__ float sv[8][16];
    const int tid = threadIdx.x;
    const int w = tid >> 5, lane = tid & 31;
    const int row = blockIdx.x * 8 + w;
    if (row >= rows) return;

    float p[16];
    #pragma unroll
    for (int j = 0; j < 16; j++) p[j] = g_projn[(size_t)row * EDIM + lane + 32 * j];

    for (int c = 0; c < 16; c++) {
        int idx = g_ci[row * 16 + c];
        const float* e = emb + (size_t)idx * EDIM;
        float s = 0.f;
        #pragma unroll
        for (int j = 0; j < 16; j++) s = fmaf(p[j], e[lane + 32 * j], s);
        #pragma unroll
        for (int o = 16; o; o >>= 1) s += __shfl_xor_sync(FULLMASK, s, o);
        if (lane == 0) sv[w][c] = s * g_einv[idx];
    }
    __syncwarp();
    if (lane == 0) {
        float tv[8]; int ti[8];
        #pragma unroll
        for (int k = 0; k < 8; k++) { tv[k] = -FLT_MAX; ti[k] = 0x7FFFFFFF; }
        for (int c = 0; c < 16; c++) {
            float f = sv[w][c]; int i = g_ci[row * 16 + c];
            if (better(f, i, tv[7], ti[7])) ins8(f, i, tv, ti);
        }
        #pragma unroll
        for (int k = 0; k < 8; k++) { g_tv[row * 8 + k] = tv[k]; g_ti[row * 8 + k] = ti[k]; }
    }
}

// ---------- gumbel-argmax sampling; float32 output ----------
__global__ void sample_kernel(int rows, float* out) {
    int r = blockIdx.x * blockDim.x + threadIdx.x;
    if (r >= rows) return;
    float best = -FLT_MAX; int bi = 0;
    #pragma unroll
    for (int k = 0; k < 8; k++) {
        float s = g_tv[r * 8 + k] + gumbel_at((unsigned)(r * 8 + k));
        if (s > best) { best = s; bi = k; }
    }
    out[r] = (float)g_ti[r * 8 + bi];
}

// ---------- launch ----------
extern "C" void kernel_launch(void* const* d_in, const int* in_sizes, int n_in,
                              void* d_out, int out_size)
{
    int pidx = 0, eidx = 1;
    if (n_in >= 2 && in_sizes[0] > in_sizes[1]) { pidx = 1; eidx = 0; }
    const float* proj = (const float*)d_in[pidx];
    const float* emb  = (const float*)d_in[eidx];

    int rows = out_size;
    if (rows <= 0 || rows > MAX_ROWS) rows = in_sizes[pidx] / EDIM;
    int V = in_sizes[eidx] / EDIM;
    if (V > MAX_V) V = MAX_V;
    float* out = (float*)d_out;

    einv_kernel<<<(V * 32 + 255) / 256, 256>>>(emb, V);
    normp_kernel<<<(rows * 32 + 255) / 256, 256>>>(proj, rows);

    dim3 grid(rows / 128, VSPLIT);
    coarse_kernel<<<grid, 512>>>(emb, V, rows);

    merge_kernel<<<(rows + 63) / 64, 64>>>(rows);
    rescore_kernel<<<(rows + 7) / 8, 256>>>(emb, rows);
    sample_kernel<<<(rows + 255) / 256, 256>>>(rows, out);
}

// round 13
// speedup vs baseline: 10.2336x; 2.2000x over previous
#include <cuda_runtime.h>
#include <cuda_bf16.h>
#include <mma.h>
#include <cstdint>
#include <float.h>
#include <math.h>

using namespace nvcuda;

#define FULLMASK 0xffffffffu
#define EDIM 512
#define MAX_ROWS 4096
#define MAX_V    50432
#define VSPLIT   9
#define NLISTS   (VSPLIT * 4)
#define KC       32                  // k-chunk (bf16)
#define ASTB     40                  // As stride (bf16 elems)
#define BSTB     40                  // Bs stride (bf16 elems)
#define WBST     20                  // extraction buffer stride (floats)

// ---------- device scratch ----------
__device__ float          g_projn[(size_t)MAX_ROWS * EDIM];   // fp32 normalized (rescore)
__device__ __nv_bfloat16  g_projb[(size_t)MAX_ROWS * EDIM];   // bf16 normalized (coarse)
__device__ __nv_bfloat16  g_embb [(size_t)MAX_V * EDIM];      // bf16 einv-scaled emb
__device__ float g_einv [MAX_V];
__device__ float g_pv   [(size_t)MAX_ROWS * NLISTS * 8];
__device__ int   g_pi   [(size_t)MAX_ROWS * NLISTS * 8];
__device__ int   g_ci   [MAX_ROWS * 16];
__device__ float g_tv   [MAX_ROWS * 8];
__device__ int   g_ti   [MAX_ROWS * 8];

// ---------- threefry-2x32, key=(0,42); partitionable xor-fold (VERIFIED) ----------
__device__ __forceinline__ void tf2x32(unsigned c0, unsigned c1,
                                       unsigned& o0, unsigned& o1) {
    unsigned x0 = c0, x1 = c1;
    const unsigned k0 = 0u, k1 = 42u, k2 = 0x1BD11BDAu ^ 0u ^ 42u;
    x0 += k0; x1 += k1;
#define TF_R(r) { x0 += x1; x1 = (x1 << (r)) | (x1 >> (32 - (r))); x1 ^= x0; }
    TF_R(13) TF_R(15) TF_R(26) TF_R(6)   x0 += k1; x1 += k2 + 1u;
    TF_R(17) TF_R(29) TF_R(16) TF_R(24)  x0 += k2; x1 += k0 + 2u;
    TF_R(13) TF_R(15) TF_R(26) TF_R(6)   x0 += k0; x1 += k1 + 3u;
    TF_R(17) TF_R(29) TF_R(16) TF_R(24)  x0 += k1; x1 += k2 + 4u;
    TF_R(13) TF_R(15) TF_R(26) TF_R(6)   x0 += k2; x1 += k0 + 5u;
#undef TF_R
    o0 = x0; o1 = x1;
}
__device__ __forceinline__ float gumbel_at(unsigned j) {
    unsigned o0, o1; tf2x32(0u, j, o0, o1);
    unsigned bits = o0 ^ o1;
    const float TINY = 1.17549435e-38f;
    float f = __uint_as_float((bits >> 9) | 0x3f800000u) - 1.0f;
    float u = fmaxf(TINY, f * (1.0f - TINY) + TINY);
    return -logf(-logf(u));
}

// ---------- prep: emb inverse-norm + bf16 scaled copy (warp / row) ----------
__global__ void prep_emb_kernel(const float* __restrict__ in, int nrows) {
    int w = (blockIdx.x * blockDim.x + threadIdx.x) >> 5;
    int lane = threadIdx.x & 31;
    if (w >= nrows) return;
    const float* x = in + (size_t)w * EDIM;
    float ss = 0.f;
    #pragma unroll
    for (int j = 0; j < 16; j++) { float v = x[lane + 32 * j]; ss += v * v; }
    #pragma unroll
    for (int o = 16; o; o >>= 1) ss += __shfl_xor_sync(FULLMASK, ss, o);
    float inv = 1.0f / fmaxf(sqrtf(ss), 1e-12f);
    if (lane == 0) g_einv[w] = inv;
    __nv_bfloat16* y = g_embb + (size_t)w * EDIM;
    #pragma unroll
    for (int j = 0; j < 16; j++) {
        int k = lane + 32 * j;
        y[k] = __float2bfloat16(x[k] * inv);
    }
}

// ---------- prep: proj normalize -> fp32 (exact) + bf16 ----------
__global__ void prep_proj_kernel(const float* __restrict__ in, int nrows) {
    int w = (blockIdx.x * blockDim.x + threadIdx.x) >> 5;
    int lane = threadIdx.x & 31;
    if (w >= nrows) return;
    const float* x = in + (size_t)w * EDIM;
    float ss = 0.f;
    #pragma unroll
    for (int j = 0; j < 16; j++) { float v = x[lane + 32 * j]; ss += v * v; }
    #pragma unroll
    for (int o = 16; o; o >>= 1) ss += __shfl_xor_sync(FULLMASK, ss, o);
    float denom = fmaxf(sqrtf(ss), 1e-12f);
    float* yf = g_projn + (size_t)w * EDIM;
    __nv_bfloat16* yb = g_projb + (size_t)w * EDIM;
    #pragma unroll
    for (int j = 0; j < 16; j++) {
        int k = lane + 32 * j;
        float v = x[k] / denom;          // IEEE div: matches reference for rescore
        yf[k] = v;
        yb[k] = __float2bfloat16(v);
    }
}

// ---------- top-k helpers (lax.top_k order) ----------
__device__ __forceinline__ bool better(float v, int i, float v2, int i2) {
    return (v > v2) || (v == v2 && i < i2);
}
__device__ __forceinline__ void ins8(float v, int i, float* tv, int* ti) {
    #pragma unroll
    for (int k = 0; k < 8; k++) {
        bool b = better(v, i, tv[k], ti[k]);
        float nv = b ? v : tv[k];  int ni = b ? i : ti[k];
        float ov = b ? tv[k] : v;  int oi = b ? ti[k] : i;
        tv[k] = nv; ti[k] = ni; v = ov; i = oi;
    }
}
__device__ __forceinline__ void ins16(float v, int i, float* tv, int* ti) {
    #pragma unroll
    for (int k = 0; k < 16; k++) {
        bool b = better(v, i, tv[k], ti[k]);
        float nv = b ? v : tv[k];  int ni = b ? i : ti[k];
        float ov = b ? tv[k] : v;  int oi = b ? ti[k] : i;
        tv[k] = nv; ti[k] = ni; v = ov; i = oi;
    }
}

// ---------- coarse bf16 WMMA GEMM + per-warp-range top-8 candidates ----------
// grid (rows/128, VSPLIT), 512 threads. Block tile 128x256, warp tile 32x64
// (2x4 m16n16k16 frags), KC=32, register double-buffered fills.
__global__ __launch_bounds__(512, 1) void coarse_kernel(int V, int rows)
{
    __shared__ float pool[16 * 32 * WBST];                  // 40 KB
    __nv_bfloat16* As = reinterpret_cast<__nv_bfloat16*>(pool);        // 128*ASTB
    __nv_bfloat16* Bs = As + 128 * ASTB;                               // 256*BSTB

    const int tid  = threadIdx.x;
    const int lane = tid & 31;
    const int w    = tid >> 5;
    const int rw   = w >> 2;
    const int cw   = w & 3;
    const int rowBase = blockIdx.x * 128;
    const int split   = blockIdx.y;

    const int vtilesTotal = (V + 255) / 256;
    const int per = (vtilesTotal + VSPLIT - 1) / VSPLIT;
    const int t0 = split * per;
    const int t1 = min(vtilesTotal, t0 + per);

    // fill assignments
    const int rA  = tid >> 2;               // 0..127
    const int kqA = (tid & 3) * 8;          // bf16 offset, 1 uint4
    const int rB  = tid >> 1;               // 0..255
    const int kqB = (tid & 1) * 16;         // 2 uint4

    float tv[8]; int ti[8];
    #pragma unroll
    for (int k = 0; k < 8; k++) { tv[k] = -FLT_MAX; ti[k] = 0x7FFFFFFF; }

    wmma::fragment<wmma::accumulator, 16, 16, 16, float> acc[2][4];

    for (int vt = t0; vt < t1; vt++) {
        const int vbase = vt * 256;
        const int vgB = vbase + rB;
        const bool okB = (vgB < V);
        const __nv_bfloat16* srcA = g_projb + (size_t)(rowBase + rA) * EDIM + kqA;
        const __nv_bfloat16* srcB = g_embb  + (size_t)(okB ? vgB : 0) * EDIM + kqB;

        #pragma unroll
        for (int f = 0; f < 2; f++)
            #pragma unroll
            for (int c = 0; c < 4; c++) wmma::fill_fragment(acc[f][c], 0.0f);

        // prefetch chunk 0
        uint4 pa, pb0, pb1;
        pa  = *reinterpret_cast<const uint4*>(srcA);
        pb0 = okB ? *reinterpret_cast<const uint4*>(srcB)
                  : make_uint4(0, 0, 0, 0);
        pb1 = okB ? *reinterpret_cast<const uint4*>(srcB + 8)
                  : make_uint4(0, 0, 0, 0);

        for (int ch = 0; ch < EDIM / KC; ch++) {
            __syncthreads();   // previous chunk MMA / prev-vtile extraction done
            *reinterpret_cast<uint4*>(As + rA * ASTB + kqA) = pa;
            *reinterpret_cast<uint4*>(Bs + rB * BSTB + kqB) = pb0;
            *reinterpret_cast<uint4*>(Bs + rB * BSTB + kqB + 8) = pb1;
            __syncthreads();

            if (ch + 1 < EDIM / KC) {      // prefetch next chunk (overlaps MMA)
                int ko = (ch + 1) * KC;
                pa  = *reinterpret_cast<const uint4*>(srcA + ko);
                pb0 = okB ? *reinterpret_cast<const uint4*>(srcB + ko)
                          : make_uint4(0, 0, 0, 0);
                pb1 = okB ? *reinterpret_cast<const uint4*>(srcB + ko + 8)
                          : make_uint4(0, 0, 0, 0);
            }

            #pragma unroll
            for (int ks = 0; ks < KC / 16; ks++) {
                wmma::fragment<wmma::matrix_a, 16, 16, 16, __nv_bfloat16,
                               wmma::row_major> fa[2];
                wmma::fragment<wmma::matrix_b, 16, 16, 16, __nv_bfloat16,
                               wmma::col_major> fb[4];
                #pragma unroll
                for (int f = 0; f < 2; f++)
                    wmma::load_matrix_sync(fa[f], As + (rw * 32 + f * 16) * ASTB + ks * 16, ASTB);
                #pragma unroll
                for (int c = 0; c < 4; c++)
                    wmma::load_matrix_sync(fb[c], Bs + (cw * 64 + c * 16) * BSTB + ks * 16, BSTB);
                #pragma unroll
                for (int f = 0; f < 2; f++)
                    #pragma unroll
                    for (int c = 0; c < 4; c++)
                        wmma::mma_sync(acc[f][c], fa[f], fb[c], acc[f][c]);
            }
        }

        __syncthreads();   // all warps done with As/Bs before pool reuse
        float* wbuf = pool + w * 32 * WBST;
        #pragma unroll
        for (int c = 0; c < 4; c++) {
            wmma::store_matrix_sync(wbuf,             acc[0][c], WBST, wmma::mem_row_major);
            wmma::store_matrix_sync(wbuf + 16 * WBST, acc[1][c], WBST, wmma::mem_row_major);
            __syncwarp();
            const float* myrow = wbuf + lane * WBST;
            #pragma unroll
            for (int j = 0; j < 16; j++) {
                int idx = vbase + cw * 64 + c * 16 + j;
                float v = myrow[j];
                if (idx < V && better(v, idx, tv[7], ti[7])) ins8(v, idx, tv, ti);
            }
            __syncwarp();
        }
    }

    {
        int row = rowBase + rw * 32 + lane;
        size_t base = ((size_t)row * NLISTS + split * 4 + cw) * 8;
        #pragma unroll
        for (int k = 0; k < 8; k++) { g_pv[base + k] = tv[k]; g_pi[base + k] = ti[k]; }
    }
}

// ---------- merge (early-break on sorted lists) -> top-16 candidates ----------
__global__ void merge_kernel(int rows) {
    int r = blockIdx.x * blockDim.x + threadIdx.x;
    if (r >= rows) return;
    float mv[16]; int mi[16];
    #pragma unroll
    for (int k = 0; k < 16; k++) { mv[k] = -FLT_MAX; mi[k] = 0x7FFFFFFF; }
    size_t rbase = (size_t)r * NLISTS * 8;
    for (int l = 0; l < NLISTS; l++) {
        size_t base = rbase + (size_t)l * 8;
        #pragma unroll
        for (int k = 0; k < 8; k++) {
            float f = g_pv[base + k]; int i = g_pi[base + k];
            if (better(f, i, mv[15], mi[15])) ins16(f, i, mv, mi);
            else break;   // list sorted by the same comparator -> rest fails too
        }
    }
    #pragma unroll
    for (int k = 0; k < 16; k++) g_ci[r * 16 + k] = mi[k];
}

// ---------- fp32 exact rescore of 16 candidates -> top-8 ----------
__global__ void rescore_kernel(const float* __restrict__ emb, int rows) {
    __shared__ float sv[8][16];
    const int tid = threadIdx.x;
    const int w = tid >> 5, lane = tid & 31;
    const int row = blockIdx.x * 8 + w;
    if (row >= rows) return;

    float p[16];
    #pragma unroll
    for (int j = 0; j < 16; j++) p[j] = g_projn[(size_t)row * EDIM + lane + 32 * j];

    for (int c = 0; c < 16; c++) {
        int idx = g_ci[row * 16 + c];
        const float* e = emb + (size_t)idx * EDIM;
        float s = 0.f;
        #pragma unroll
        for (int j = 0; j < 16; j++) s = fmaf(p[j], e[lane + 32 * j], s);
        #pragma unroll
        for (int o = 16; o; o >>= 1) s += __shfl_xor_sync(FULLMASK, s, o);
        if (lane == 0) sv[w][c] = s * g_einv[idx];
    }
    __syncwarp();
    if (lane == 0) {
        float tv[8]; int ti[8];
        #pragma unroll
        for (int k = 0; k < 8; k++) { tv[k] = -FLT_MAX; ti[k] = 0x7FFFFFFF; }
        for (int c = 0; c < 16; c++) {
            float f = sv[w][c]; int i = g_ci[row * 16 + c];
            if (better(f, i, tv[7], ti[7])) ins8(f, i, tv, ti);
        }
        #pragma unroll
        for (int k = 0; k < 8; k++) { g_tv[row * 8 + k] = tv[k]; g_ti[row * 8 + k] = ti[k]; }
    }
}

// ---------- gumbel-argmax sampling; float32 output ----------
__global__ void sample_kernel(int rows, float* out) {
    int r = blockIdx.x * blockDim.x + threadIdx.x;
    if (r >= rows) return;
    float best = -FLT_MAX; int bi = 0;
    #pragma unroll
    for (int k = 0; k < 8; k++) {
        float s = g_tv[r * 8 + k] + gumbel_at((unsigned)(r * 8 + k));
        if (s > best) { best = s; bi = k; }
    }
    out[r] = (float)g_ti[r * 8 + bi];
}

// ---------- launch ----------
extern "C" void kernel_launch(void* const* d_in, const int* in_sizes, int n_in,
                              void* d_out, int out_size)
{
    int pidx = 0, eidx = 1;
    if (n_in >= 2 && in_sizes[0] > in_sizes[1]) { pidx = 1; eidx = 0; }
    const float* proj = (const float*)d_in[pidx];
    const float* emb  = (const float*)d_in[eidx];

    int rows = out_size;
    if (rows <= 0 || rows > MAX_ROWS) rows = in_sizes[pidx] / EDIM;
    int V = in_sizes[eidx] / EDIM;
    if (V > MAX_V) V = MAX_V;
    float* out = (float*)d_out;

    prep_emb_kernel <<<(V * 32 + 255) / 256, 256>>>(emb, V);
    prep_proj_kernel<<<(rows * 32 + 255) / 256, 256>>>(proj, rows);

    dim3 grid(rows / 128, VSPLIT);
    coarse_kernel<<<grid, 512>>>(V, rows);

    merge_kernel<<<(rows + 127) / 128, 128>>>(rows);
    rescore_kernel<<<(rows + 7) / 8, 256>>>(emb, rows);
    sample_kernel<<<(rows + 255) / 256, 256>>>(rows, out);
}